// round 15
// baseline (speedup 1.0000x reference)
#include <cuda_runtime.h>
#include <cstdint>

#define HEADS   8
#define DH      32
#define MLEN    1024
#define NPROB   64          // B * HEADS * RATE
#define BATCH   4
#define SEQ     2046
#define NPAD    2048
#define DMODEL  256

#define BM      64
#define BN      64
#define OPITCH  34          // Obuf pitch

__device__ float g_qkv[NPROB * MLEN * DH];

// ---------------------------------------------------------------------------
// helpers
// ---------------------------------------------------------------------------
__device__ __forceinline__ uint32_t f2tf32(float f) {
  uint32_t u;
  asm("cvt.rna.tf32.f32 %0, %1;" : "=r"(u) : "f"(f));
  return u;
}

__device__ __forceinline__ float ex2(float x) {
  float r;
  asm("ex2.approx.f32 %0, %1;" : "=f"(r) : "f"(x));
  return r;
}

__device__ __forceinline__ void mma_tf32(float c[4],
    uint32_t a0, uint32_t a1, uint32_t a2, uint32_t a3,
    uint32_t b0, uint32_t b1) {
  asm volatile(
    "mma.sync.aligned.m16n8k8.row.col.f32.tf32.tf32.f32 "
    "{%0,%1,%2,%3},{%4,%5,%6,%7},{%8,%9},{%0,%1,%2,%3};"
    : "+f"(c[0]), "+f"(c[1]), "+f"(c[2]), "+f"(c[3])
    : "r"(a0), "r"(a1), "r"(a2), "r"(a3), "r"(b0), "r"(b1));
}

__device__ __forceinline__ void cp16(uint32_t dst_smem, const void* src) {
  asm volatile("cp.async.cg.shared.global [%0], [%1], 16;"
               :: "r"(dst_smem), "l"(src));
}
__device__ __forceinline__ void cp_commit() {
  asm volatile("cp.async.commit_group;");
}
__device__ __forceinline__ void cp_wait0() {
  asm volatile("cp.async.wait_group 0;");
}

// ---------------------------------------------------------------------------
// Kernel 1: qkv = pad(x) @ W + b (tf32). K=64 chunks (4 instead of 8):
// halves the exposed LDG rounds and barrier count. Single 48KB smem buffer
// (grid is single-wave; smem occupancy irrelevant). Same rna conversions and
// k-step order as before -> bit-identical results.
// ---------------------------------------------------------------------------
__global__ __launch_bounds__(256) void qkv_gemm(
    const float* __restrict__ x, const float* __restrict__ W,
    const float* __restrict__ bias) {
  __shared__ __align__(16) uint32_t Xs[128 * 64];   // 32 KB
  __shared__ __align__(16) uint32_t Ws[64 * 64];    // 16 KB
  const int m0 = blockIdx.x * 128;
  const int n0 = blockIdx.y * 64;
  const int tid = threadIdx.x;
  const int warp = tid >> 5, lane = tid & 31;
  const int wm = warp >> 1, wn = warp & 1;
  const int qrow = lane >> 2, qk = lane & 3;
  const uint32_t swzA = (uint32_t)(qrow << 2);

  float C[2][4][4];
  #pragma unroll
  for (int i = 0; i < 2; ++i)
    #pragma unroll
    for (int j = 0; j < 4; ++j)
      #pragma unroll
      for (int k = 0; k < 4; ++k) C[i][j][k] = 0.0f;

  for (int kc0 = 0; kc0 < DMODEL; kc0 += 64) {
    // ---- fill Xs[128][64] (tf32, swizzled); padded rows -> 0 ----
    #pragma unroll
    for (int e = 0; e < 8; ++e) {
      int f = tid + 256 * e;            // 2048 float4 groups
      int r = f >> 4, c4 = (f & 15) << 2;
      int m = m0 + r;
      int b = m >> 11, n = m & 2047;
      uint4 u = make_uint4(0u, 0u, 0u, 0u);
      if (n < SEQ) {
        float4 v = *reinterpret_cast<const float4*>(
            x + ((size_t)b * SEQ + n) * DMODEL + kc0 + c4);
        u.x = f2tf32(v.x); u.y = f2tf32(v.y);
        u.z = f2tf32(v.z); u.w = f2tf32(v.w);
      }
      *reinterpret_cast<uint4*>(&Xs[r * 64 + (c4 ^ ((r & 7) << 2))]) = u;
    }
    // ---- fill Ws[64][64] = W^T tile: coalesced read, transposed store ----
    #pragma unroll
    for (int e = 0; e < 4; ++e) {
      int u = tid + 256 * e;            // 1024 float4 groups
      int c = u >> 4, r4 = (u & 15) << 2;
      float4 v = *reinterpret_cast<const float4*>(
          W + (size_t)(kc0 + c) * DMODEL + n0 + r4);
      Ws[(r4 + 0) * 64 + (c ^ (((r4 + 0) & 7) << 2))] = f2tf32(v.x);
      Ws[(r4 + 1) * 64 + (c ^ (((r4 + 1) & 7) << 2))] = f2tf32(v.y);
      Ws[(r4 + 2) * 64 + (c ^ (((r4 + 2) & 7) << 2))] = f2tf32(v.z);
      Ws[(r4 + 3) * 64 + (c ^ (((r4 + 3) & 7) << 2))] = f2tf32(v.w);
    }
    __syncthreads();

    #pragma unroll
    for (int ks = 0; ks < 8; ++ks) {
      const int k0 = ks * 8 + qk;
      uint32_t a[2][4];
      #pragma unroll
      for (int mt = 0; mt < 2; ++mt) {
        const int rb = wm * 32 + mt * 16 + qrow;
        a[mt][0] = Xs[rb * 64 + (k0 ^ swzA)];
        a[mt][1] = Xs[(rb + 8) * 64 + (k0 ^ swzA)];
        a[mt][2] = Xs[rb * 64 + ((k0 + 4) ^ swzA)];
        a[mt][3] = Xs[(rb + 8) * 64 + ((k0 + 4) ^ swzA)];
      }
      uint32_t bf[4][2];
      #pragma unroll
      for (int nt = 0; nt < 4; ++nt) {
        const int nc = wn * 32 + nt * 8 + qrow;
        bf[nt][0] = Ws[nc * 64 + (k0 ^ swzA)];
        bf[nt][1] = Ws[nc * 64 + ((k0 + 4) ^ swzA)];
      }
      #pragma unroll
      for (int mt = 0; mt < 2; ++mt)
        #pragma unroll
        for (int nt = 0; nt < 4; ++nt)
          mma_tf32(C[mt][nt], a[mt][0], a[mt][1], a[mt][2], a[mt][3],
                   bf[nt][0], bf[nt][1]);
    }
    __syncthreads();
  }

  #pragma unroll
  for (int nt = 0; nt < 4; ++nt) {
    const int col = n0 + wn * 32 + nt * 8 + 2 * qk;
    const float bx = bias[col], by = bias[col + 1];
    const int h = col >> 5, dd = col & 31;
    #pragma unroll
    for (int mt = 0; mt < 2; ++mt) {
      #pragma unroll
      for (int half = 0; half < 2; ++half) {
        const int r = wm * 32 + mt * 16 + half * 8 + qrow;
        const int m = m0 + r;
        const int b = m >> 11, n = m & 2047;
        const int i = n >> 1, rbit = n & 1;
        float2 val = make_float2(C[mt][nt][half * 2 + 0] + bx,
                                 C[mt][nt][half * 2 + 1] + by);
        *reinterpret_cast<float2*>(
            &g_qkv[((((size_t)b * HEADS + h) * 2 + rbit) * MLEN + i) * DH + dd]) =
            val;
      }
    }
  }
}

// ---------------------------------------------------------------------------
// Kernel 2: flash attention — byte-identical to R12/R14 (79.9us).
// ---------------------------------------------------------------------------
__global__ __launch_bounds__(128, 4) void attn(float* __restrict__ out) {
  const int blk  = blockIdx.x;
  const int prob = blk >> 4;
  const int tile = blk & 15;
  const int t0   = tile * BM;
  const int rbit = prob & 1;
  const int h    = (prob >> 1) & 7;
  const int b    = prob >> 4;
  const float* __restrict__ base = g_qkv + (size_t)prob * (MLEN * DH);
  const int tid  = threadIdx.x;
  const int warp = tid >> 5, lane = tid & 31;
  const int wm = warp >> 1, wn = warp & 1;
  const int qrow = lane >> 2, qk = lane & 3;
  const uint32_t swzA = (uint32_t)(qrow << 2);
  const float scale2 = 0.17677669529663687f * 1.4426950408889634f;

  __shared__ __align__(16) char KsObuf[BM * OPITCH * 4];   // Ks then Obuf
  __shared__ __align__(16) uint32_t Qs[2][BN * 32];
  __shared__ float rowLp[2 * BM];
  __shared__ float pe0[BM], pe1[BM], pe2[BM], linv[BM];
  uint32_t* Ks  = reinterpret_cast<uint32_t*>(KsObuf);
  float*   Obuf = reinterpret_cast<float*>(KsObuf);

  const uint32_t qsBase = (uint32_t)__cvta_generic_to_shared(&Qs[0][0]);

  // ---- async-fill Qs[0] (raw fp32; tf32 MMA truncates) ----
  #pragma unroll
  for (int e = 0; e < 4; ++e) {
    int f = tid + 128 * e;
    int r = f >> 3, c = (f & 7) << 2;
    cp16(qsBase + (uint32_t)(r * 32 + (c ^ ((r & 7) << 2))) * 4,
         base + (size_t)r * DH + c);
  }
  cp_commit();

  // ---- fill Ks (scaled by scale*log2e, tf32, swizzled) ----
  #pragma unroll
  for (int e = 0; e < 4; ++e) {
    int f = tid + 128 * e;
    int r = f >> 3, c = (f & 7) << 2;
    float4 v = *reinterpret_cast<const float4*>(base + (size_t)(t0 + r) * DH + c);
    uint4 u;
    u.x = f2tf32(v.x * scale2); u.y = f2tf32(v.y * scale2);
    u.z = f2tf32(v.z * scale2); u.w = f2tf32(v.w * scale2);
    *reinterpret_cast<uint4*>(&Ks[r * 32 + (c ^ ((r & 7) << 2))]) = u;
  }
  cp_wait0();
  __syncthreads();

  // ---- hoist K A-fragments (Ks dead afterwards -> Obuf reuses its smem) ----
  uint32_t A[2][4][4];
  #pragma unroll
  for (int mt = 0; mt < 2; ++mt) {
    const int rb = wm * 32 + mt * 16 + qrow;
    #pragma unroll
    for (int kc = 0; kc < 4; ++kc) {
      const int k0 = kc * 8 + qk;
      A[mt][kc][0] = Ks[rb * 32 + (k0 ^ swzA)];
      A[mt][kc][1] = Ks[(rb + 8) * 32 + (k0 ^ swzA)];
      A[mt][kc][2] = Ks[rb * 32 + ((k0 + 4) ^ swzA)];
      A[mt][kc][3] = Ks[(rb + 8) * 32 + ((k0 + 4) ^ swzA)];
    }
  }
  __syncthreads();   // all warps done reading Ks before Obuf writes

  float O[2][4][4];
  #pragma unroll
  for (int i = 0; i < 2; ++i)
    #pragma unroll
    for (int j = 0; j < 4; ++j)
      #pragma unroll
      for (int k = 0; k < 4; ++k) O[i][j][k] = 0.0f;
  float rsum[4] = {0.f, 0.f, 0.f, 0.f};

  for (int it = 0; it < MLEN / BN; ++it) {
    const uint32_t* __restrict__ Qc = Qs[it & 1];

    // ---- async-fill NEXT tile (data lands during compute) ----
    if (it < MLEN / BN - 1) {
      const float* nsrc = base + (size_t)(it + 1) * BN * DH;
      const uint32_t dstBase = qsBase + (uint32_t)(((it + 1) & 1) * BN * 32) * 4;
      #pragma unroll
      for (int e = 0; e < 4; ++e) {
        int f = tid + 128 * e;
        int r = f >> 3, c = (f & 7) << 2;
        cp16(dstBase + (uint32_t)(r * 32 + (c ^ ((r & 7) << 2))) * 4,
             nsrc + r * 32 + c);
      }
    }
    cp_commit();

    #pragma unroll
    for (int g = 0; g < 4; ++g) {
      float acc[2][4] = {{0.f,0.f,0.f,0.f},{0.f,0.f,0.f,0.f}};
      const int nc = wn * 32 + g * 8 + qrow;
      #pragma unroll
      for (int kc = 0; kc < 4; ++kc) {
        const int k0 = kc * 8 + qk;
        uint32_t b0 = Qc[nc * 32 + (k0 ^ swzA)];
        uint32_t b1 = Qc[nc * 32 + ((k0 + 4) ^ swzA)];
        mma_tf32(acc[0], A[0][kc][0], A[0][kc][1], A[0][kc][2], A[0][kc][3], b0, b1);
        mma_tf32(acc[1], A[1][kc][0], A[1][kc][1], A[1][kc][2], A[1][kc][3], b0, b1);
      }

      // ---- exp2 (single MUFU), row-sum; P bits fed RAW to tf32 MMA ----
      uint32_t aP[2][4];
      #pragma unroll
      for (int mt = 0; mt < 2; ++mt) {
        float p0 = ex2(acc[mt][0]);
        float p1 = ex2(acc[mt][1]);
        float p2 = ex2(acc[mt][2]);
        float p3 = ex2(acc[mt][3]);
        rsum[mt * 2 + 0] += p0 + p1;
        rsum[mt * 2 + 1] += p2 + p3;
        aP[mt][0] = __float_as_uint(p0);
        aP[mt][1] = __float_as_uint(p2);
        aP[mt][2] = __float_as_uint(p1);
        aP[mt][3] = __float_as_uint(p3);
      }

      const int jr0 = wn * 32 + g * 8 + 2 * qk;
      const int jr1 = jr0 + 1;
      const uint32_t swz0 = (uint32_t)((jr0 & 7) << 2);
      const uint32_t swz1 = (uint32_t)((jr1 & 7) << 2);
      #pragma unroll
      for (int ntd = 0; ntd < 4; ++ntd) {
        const int d = ntd * 8 + qrow;
        uint32_t vb0 = Qc[jr0 * 32 + (d ^ swz0)];
        uint32_t vb1 = Qc[jr1 * 32 + (d ^ swz1)];
        mma_tf32(O[0][ntd], aP[0][0], aP[0][1], aP[0][2], aP[0][3], vb0, vb1);
        mma_tf32(O[1][ntd], aP[1][0], aP[1][1], aP[1][2], aP[1][3], vb0, vb1);
      }
    }
    cp_wait0();
    __syncthreads();
  }

  #pragma unroll
  for (int s = 0; s < 4; ++s) {
    rsum[s] += __shfl_xor_sync(0xffffffffu, rsum[s], 1);
    rsum[s] += __shfl_xor_sync(0xffffffffu, rsum[s], 2);
  }
  if (qk == 0) {
    #pragma unroll
    for (int s = 0; s < 4; ++s) {
      int r = wm * 32 + (s >> 1) * 16 + (s & 1) * 8 + qrow;
      rowLp[wn * BM + r] = rsum[s];
    }
  }

  if (wn == 1) {
    #pragma unroll
    for (int mt = 0; mt < 2; ++mt) {
      const int r = wm * 32 + mt * 16 + qrow;
      #pragma unroll
      for (int ntd = 0; ntd < 4; ++ntd) {
        const int cb = ntd * 8 + 2 * qk;
        *reinterpret_cast<float2*>(&Obuf[r * OPITCH + cb]) =
            make_float2(O[mt][ntd][0], O[mt][ntd][1]);
        *reinterpret_cast<float2*>(&Obuf[(r + 8) * OPITCH + cb]) =
            make_float2(O[mt][ntd][2], O[mt][ntd][3]);
      }
    }
  }
  __syncthreads();

  if (tid < BM) {
    const int row = tid;
    const int t = t0 + row;
    const float* qt = base + (size_t)t * DH;
    float d0 = 0.f, d1 = 0.f, d2 = 0.f;
    #pragma unroll
    for (int kk = 0; kk < DH; ++kk) { float q = qt[kk]; d1 = fmaf(q, q, d1); }
    if (t > 0) {
      const float* km = base + (size_t)(t - 1) * DH;
      #pragma unroll
      for (int kk = 0; kk < DH; ++kk) d0 = fmaf(qt[kk], km[kk], d0);
    }
    if (t < MLEN - 1) {
      const float* kp = base + (size_t)(t + 1) * DH;
      #pragma unroll
      for (int kk = 0; kk < DH; ++kk) d2 = fmaf(qt[kk], kp[kk], d2);
    }
    float e0 = (t > 0)        ? d0 * scale2 : 0.0f;
    float e1 = d1 * scale2;
    float e2 = (t < MLEN - 1) ? d2 * scale2 : 0.0f;
    float p0 = ex2(e0), p1 = ex2(e1), p2 = ex2(e2);
    float L = rowLp[row] + rowLp[BM + row] + p0 + p1 + p2;
    pe0[row] = (t > 0)        ? p0 : 0.0f;
    pe1[row] = p1;
    pe2[row] = (t < MLEN - 1) ? p2 : 0.0f;
    linv[row] = 1.0f / L;
  }
  __syncthreads();

  if (wn == 0) {
    #pragma unroll
    for (int mt = 0; mt < 2; ++mt) {
      #pragma unroll
      for (int half = 0; half < 2; ++half) {
        const int r = wm * 32 + mt * 16 + half * 8 + qrow;
        const int t = t0 + r;
        const int n = 2 * t + rbit;
        if (n >= SEQ) continue;
        const float inv = linv[r];
        const float w0 = pe0[r], w1 = pe1[r], w2 = pe2[r];
        #pragma unroll
        for (int ntd = 0; ntd < 4; ++ntd) {
          const int cb = ntd * 8 + 2 * qk;
          float2 oo = *reinterpret_cast<const float2*>(&Obuf[r * OPITCH + cb]);
          float ax = O[mt][ntd][half * 2 + 0] + oo.x;
          float ay = O[mt][ntd][half * 2 + 1] + oo.y;
          float2 vc = *reinterpret_cast<const float2*>(&base[(size_t)t * DH + cb]);
          ax = fmaf(w1, vc.x, ax);
          ay = fmaf(w1, vc.y, ay);
          if (t > 0) {
            float2 vm = *reinterpret_cast<const float2*>(&base[(size_t)(t - 1) * DH + cb]);
            ax = fmaf(w0, vm.x, ax);
            ay = fmaf(w0, vm.y, ay);
          }
          if (t < MLEN - 1) {
            float2 vp = *reinterpret_cast<const float2*>(&base[(size_t)(t + 1) * DH + cb]);
            ax = fmaf(w2, vp.x, ax);
            ay = fmaf(w2, vp.y, ay);
          }
          *reinterpret_cast<float2*>(
              &out[((size_t)b * SEQ + n) * DMODEL + h * DH + cb]) =
              make_float2(ax * inv, ay * inv);
        }
      }
    }
  }
}

// ---------------------------------------------------------------------------
extern "C" void kernel_launch(void* const* d_in, const int* in_sizes, int n_in,
                              void* d_out, int out_size) {
  const float* x    = (const float*)d_in[0];
  const float* W    = (const float*)d_in[1];
  const float* bias = (const float*)d_in[2];
  float* out = (float*)d_out;

  qkv_gemm<<<dim3(BATCH * NPAD / 128, DMODEL / 64), 256>>>(x, W, bias);
  attn<<<NPROB * (MLEN / BM), 128>>>(out);
}

// round 16
// speedup vs baseline: 1.0074x; 1.0074x over previous
#include <cuda_runtime.h>
#include <cstdint>

#define HEADS   8
#define DH      32
#define MLEN    1024
#define NPROB   64          // B * HEADS * RATE
#define BATCH   4
#define SEQ     2046
#define NPAD    2048
#define DMODEL  256

#define BM      64
#define BN      64
#define OPITCH  34          // Obuf pitch

__device__ float g_qkv[NPROB * MLEN * DH];

// ---------------------------------------------------------------------------
// helpers
// ---------------------------------------------------------------------------
__device__ __forceinline__ uint32_t f2tf32(float f) {
  uint32_t u;
  asm("cvt.rna.tf32.f32 %0, %1;" : "=r"(u) : "f"(f));
  return u;
}

__device__ __forceinline__ float ex2(float x) {
  float r;
  asm("ex2.approx.f32 %0, %1;" : "=f"(r) : "f"(x));
  return r;
}

__device__ __forceinline__ void mma_tf32(float c[4],
    uint32_t a0, uint32_t a1, uint32_t a2, uint32_t a3,
    uint32_t b0, uint32_t b1) {
  asm volatile(
    "mma.sync.aligned.m16n8k8.row.col.f32.tf32.tf32.f32 "
    "{%0,%1,%2,%3},{%4,%5,%6,%7},{%8,%9},{%0,%1,%2,%3};"
    : "+f"(c[0]), "+f"(c[1]), "+f"(c[2]), "+f"(c[3])
    : "r"(a0), "r"(a1), "r"(a2), "r"(a3), "r"(b0), "r"(b1));
}

__device__ __forceinline__ void cp16(uint32_t dst_smem, const void* src) {
  asm volatile("cp.async.cg.shared.global [%0], [%1], 16;"
               :: "r"(dst_smem), "l"(src));
}
__device__ __forceinline__ void cp_commit() {
  asm volatile("cp.async.commit_group;");
}
__device__ __forceinline__ void cp_wait1() {
  asm volatile("cp.async.wait_group 1;");
}

// ---------------------------------------------------------------------------
// Kernel 1: qkv = pad(x) @ W + b (tf32). SINGLE-buffer register prefetch
// (exact R14 code — best measured): chunk k+1's LDGs issue at the top of
// chunk k's MMA phase; cvt+STS after the post-MMA barrier into the same
// buffer.
// ---------------------------------------------------------------------------
__global__ __launch_bounds__(256, 2) void qkv_gemm(
    const float* __restrict__ x, const float* __restrict__ W,
    const float* __restrict__ bias) {
  __shared__ __align__(16) uint32_t Xs[128 * 32];
  __shared__ __align__(16) uint32_t Ws[64 * 32];
  const int m0 = blockIdx.x * 128;
  const int n0 = blockIdx.y * 64;
  const int tid = threadIdx.x;
  const int warp = tid >> 5, lane = tid & 31;
  const int wm = warp >> 1, wn = warp & 1;
  const int qrow = lane >> 2, qk = lane & 3;
  const uint32_t swzA = (uint32_t)(qrow << 2);

  int xr_[4], xc_[4], xb_[4], xn_[4];
  #pragma unroll
  for (int e = 0; e < 4; ++e) {
    int f = tid + 256 * e;
    xr_[e] = f >> 3; xc_[e] = (f & 7) << 2;
    int m = m0 + xr_[e];
    xb_[e] = m >> 11; xn_[e] = m & 2047;
  }
  int wc_[2], wr4_[2];
  #pragma unroll
  for (int e = 0; e < 2; ++e) {
    int u = tid + 256 * e;
    wc_[e] = u >> 4; wr4_[e] = (u & 15) << 2;
  }

  float4 xv[4], wv[2];
  auto loadRegs = [&](int kc0) {
    #pragma unroll
    for (int e = 0; e < 4; ++e) {
      if (xn_[e] < SEQ)
        xv[e] = *reinterpret_cast<const float4*>(
            x + ((size_t)xb_[e] * SEQ + xn_[e]) * DMODEL + kc0 + xc_[e]);
      else
        xv[e] = make_float4(0.f, 0.f, 0.f, 0.f);
    }
    #pragma unroll
    for (int e = 0; e < 2; ++e)
      wv[e] = *reinterpret_cast<const float4*>(
          W + (size_t)(kc0 + wc_[e]) * DMODEL + n0 + wr4_[e]);
  };
  auto storeRegs = [&]() {
    #pragma unroll
    for (int e = 0; e < 4; ++e) {
      int r = xr_[e], c4 = xc_[e];
      uint4 u;
      u.x = f2tf32(xv[e].x); u.y = f2tf32(xv[e].y);
      u.z = f2tf32(xv[e].z); u.w = f2tf32(xv[e].w);
      *reinterpret_cast<uint4*>(&Xs[r * 32 + (c4 ^ ((r & 7) << 2))]) = u;
    }
    #pragma unroll
    for (int e = 0; e < 2; ++e) {
      int c = wc_[e], r4 = wr4_[e];
      Ws[(r4 + 0) * 32 + (c ^ (((r4 + 0) & 7) << 2))] = f2tf32(wv[e].x);
      Ws[(r4 + 1) * 32 + (c ^ (((r4 + 1) & 7) << 2))] = f2tf32(wv[e].y);
      Ws[(r4 + 2) * 32 + (c ^ (((r4 + 2) & 7) << 2))] = f2tf32(wv[e].z);
      Ws[(r4 + 3) * 32 + (c ^ (((r4 + 3) & 7) << 2))] = f2tf32(wv[e].w);
    }
  };

  float C[2][4][4];
  #pragma unroll
  for (int i = 0; i < 2; ++i)
    #pragma unroll
    for (int j = 0; j < 4; ++j)
      #pragma unroll
      for (int k = 0; k < 4; ++k) C[i][j][k] = 0.0f;

  loadRegs(0);
  storeRegs();
  __syncthreads();

  for (int kc = 0; kc < 8; ++kc) {
    if (kc < 7) loadRegs((kc + 1) * 32);

    #pragma unroll
    for (int ks = 0; ks < 4; ++ks) {
      const int k0 = ks * 8 + qk;
      uint32_t a[2][4];
      #pragma unroll
      for (int mt = 0; mt < 2; ++mt) {
        const int rb = wm * 32 + mt * 16 + qrow;
        a[mt][0] = Xs[rb * 32 + (k0 ^ swzA)];
        a[mt][1] = Xs[(rb + 8) * 32 + (k0 ^ swzA)];
        a[mt][2] = Xs[rb * 32 + ((k0 + 4) ^ swzA)];
        a[mt][3] = Xs[(rb + 8) * 32 + ((k0 + 4) ^ swzA)];
      }
      uint32_t bf[4][2];
      #pragma unroll
      for (int nt = 0; nt < 4; ++nt) {
        const int nc = wn * 32 + nt * 8 + qrow;
        bf[nt][0] = Ws[nc * 32 + (k0 ^ swzA)];
        bf[nt][1] = Ws[nc * 32 + ((k0 + 4) ^ swzA)];
      }
      #pragma unroll
      for (int mt = 0; mt < 2; ++mt)
        #pragma unroll
        for (int nt = 0; nt < 4; ++nt)
          mma_tf32(C[mt][nt], a[mt][0], a[mt][1], a[mt][2], a[mt][3],
                   bf[nt][0], bf[nt][1]);
    }

    if (kc < 7) {
      __syncthreads();
      storeRegs();
      __syncthreads();
    }
  }

  #pragma unroll
  for (int nt = 0; nt < 4; ++nt) {
    const int col = n0 + wn * 32 + nt * 8 + 2 * qk;
    const float bx = bias[col], by = bias[col + 1];
    const int h = col >> 5, dd = col & 31;
    #pragma unroll
    for (int mt = 0; mt < 2; ++mt) {
      #pragma unroll
      for (int half = 0; half < 2; ++half) {
        const int r = wm * 32 + mt * 16 + half * 8 + qrow;
        const int m = m0 + r;
        const int b = m >> 11, n = m & 2047;
        const int i = n >> 1, rbit = n & 1;
        float2 val = make_float2(C[mt][nt][half * 2 + 0] + bx,
                                 C[mt][nt][half * 2 + 1] + by);
        *reinterpret_cast<float2*>(
            &g_qkv[((((size_t)b * HEADS + h) * 2 + rbit) * MLEN + i) * DH + dd]) =
            val;
      }
    }
  }
}

// ---------------------------------------------------------------------------
// Kernel 2: flash attention — R12/R14 structure with TRIPLE-buffered tiles:
// wait_group 1 at loop top completes tile `it` while tile it+1 stays in
// flight (a full iteration of latency slack); one barrier per tile; tile
// it+2 is issued into the buffer whose readers finished two iterations ago.
// Numerics identical to R14 (raw-bit P, ex2.approx).
// ---------------------------------------------------------------------------
__global__ __launch_bounds__(128, 4) void attn(float* __restrict__ out) {
  const int blk  = blockIdx.x;
  const int prob = blk >> 4;
  const int tile = blk & 15;
  const int t0   = tile * BM;
  const int rbit = prob & 1;
  const int h    = (prob >> 1) & 7;
  const int b    = prob >> 4;
  const float* __restrict__ base = g_qkv + (size_t)prob * (MLEN * DH);
  const int tid  = threadIdx.x;
  const int warp = tid >> 5, lane = tid & 31;
  const int wm = warp >> 1, wn = warp & 1;
  const int qrow = lane >> 2, qk = lane & 3;
  const uint32_t swzA = (uint32_t)(qrow << 2);
  const float scale2 = 0.17677669529663687f * 1.4426950408889634f;

  __shared__ __align__(16) char KsObuf[BM * OPITCH * 4];   // Ks then Obuf
  __shared__ __align__(16) uint32_t Qs[3][BN * 32];        // triple buffer
  __shared__ float rowLp[2 * BM];
  __shared__ float pe0[BM], pe1[BM], pe2[BM], linv[BM];
  uint32_t* Ks  = reinterpret_cast<uint32_t*>(KsObuf);
  float*   Obuf = reinterpret_cast<float*>(KsObuf);

  const uint32_t qsBase = (uint32_t)__cvta_generic_to_shared(&Qs[0][0]);

  // ---- per-thread tile-fill (raw fp32; tf32 MMA truncates) ----
  auto issueTile = [&](int it, int buf) {
    const float* src = base + (size_t)it * BN * DH;
    const uint32_t dst = qsBase + (uint32_t)(buf * BN * 32) * 4;
    #pragma unroll
    for (int e = 0; e < 4; ++e) {
      int f = tid + 128 * e;
      int r = f >> 3, c = (f & 7) << 2;
      cp16(dst + (uint32_t)(r * 32 + (c ^ ((r & 7) << 2))) * 4,
           src + r * 32 + c);
    }
  };

  // ---- prologue: tiles 0 and 1 in flight ----
  issueTile(0, 0); cp_commit();
  issueTile(1, 1); cp_commit();

  // ---- fill Ks (scaled by scale*log2e, tf32, swizzled) ----
  #pragma unroll
  for (int e = 0; e < 4; ++e) {
    int f = tid + 128 * e;
    int r = f >> 3, c = (f & 7) << 2;
    float4 v = *reinterpret_cast<const float4*>(base + (size_t)(t0 + r) * DH + c);
    uint4 u;
    u.x = f2tf32(v.x * scale2); u.y = f2tf32(v.y * scale2);
    u.z = f2tf32(v.z * scale2); u.w = f2tf32(v.w * scale2);
    *reinterpret_cast<uint4*>(&Ks[r * 32 + (c ^ ((r & 7) << 2))]) = u;
  }
  __syncthreads();

  // ---- hoist K A-fragments (Ks dead afterwards -> Obuf reuses its smem) ----
  uint32_t A[2][4][4];
  #pragma unroll
  for (int mt = 0; mt < 2; ++mt) {
    const int rb = wm * 32 + mt * 16 + qrow;
    #pragma unroll
    for (int kc = 0; kc < 4; ++kc) {
      const int k0 = kc * 8 + qk;
      A[mt][kc][0] = Ks[rb * 32 + (k0 ^ swzA)];
      A[mt][kc][1] = Ks[(rb + 8) * 32 + (k0 ^ swzA)];
      A[mt][kc][2] = Ks[rb * 32 + ((k0 + 4) ^ swzA)];
      A[mt][kc][3] = Ks[(rb + 8) * 32 + ((k0 + 4) ^ swzA)];
    }
  }
  __syncthreads();   // all warps done reading Ks before Obuf writes

  float O[2][4][4];
  #pragma unroll
  for (int i = 0; i < 2; ++i)
    #pragma unroll
    for (int j = 0; j < 4; ++j)
      #pragma unroll
      for (int k = 0; k < 4; ++k) O[i][j][k] = 0.0f;
  float rsum[4] = {0.f, 0.f, 0.f, 0.f};

  for (int it = 0; it < MLEN / BN; ++it) {
    cp_wait1();        // tile `it` complete; tile it+1 may still be in flight
    __syncthreads();   // publish tile it; buf (it+2)%3's readers are done

    if (it + 2 < MLEN / BN) issueTile(it + 2, (it + 2) % 3);
    cp_commit();       // exactly one group per iteration (may be empty)

    const uint32_t* __restrict__ Qc = &Qs[it % 3][0];

    #pragma unroll
    for (int g = 0; g < 4; ++g) {
      float acc[2][4] = {{0.f,0.f,0.f,0.f},{0.f,0.f,0.f,0.f}};
      const int nc = wn * 32 + g * 8 + qrow;
      #pragma unroll
      for (int kc = 0; kc < 4; ++kc) {
        const int k0 = kc * 8 + qk;
        uint32_t b0 = Qc[nc * 32 + (k0 ^ swzA)];
        uint32_t b1 = Qc[nc * 32 + ((k0 + 4) ^ swzA)];
        mma_tf32(acc[0], A[0][kc][0], A[0][kc][1], A[0][kc][2], A[0][kc][3], b0, b1);
        mma_tf32(acc[1], A[1][kc][0], A[1][kc][1], A[1][kc][2], A[1][kc][3], b0, b1);
      }

      // ---- exp2 (single MUFU), row-sum; P bits fed RAW to tf32 MMA ----
      uint32_t aP[2][4];
      #pragma unroll
      for (int mt = 0; mt < 2; ++mt) {
        float p0 = ex2(acc[mt][0]);
        float p1 = ex2(acc[mt][1]);
        float p2 = ex2(acc[mt][2]);
        float p3 = ex2(acc[mt][3]);
        rsum[mt * 2 + 0] += p0 + p1;
        rsum[mt * 2 + 1] += p2 + p3;
        aP[mt][0] = __float_as_uint(p0);
        aP[mt][1] = __float_as_uint(p2);
        aP[mt][2] = __float_as_uint(p1);
        aP[mt][3] = __float_as_uint(p3);
      }

      const int jr0 = wn * 32 + g * 8 + 2 * qk;
      const int jr1 = jr0 + 1;
      const uint32_t swz0 = (uint32_t)((jr0 & 7) << 2);
      const uint32_t swz1 = (uint32_t)((jr1 & 7) << 2);
      #pragma unroll
      for (int ntd = 0; ntd < 4; ++ntd) {
        const int d = ntd * 8 + qrow;
        uint32_t vb0 = Qc[jr0 * 32 + (d ^ swz0)];
        uint32_t vb1 = Qc[jr1 * 32 + (d ^ swz1)];
        mma_tf32(O[0][ntd], aP[0][0], aP[0][1], aP[0][2], aP[0][3], vb0, vb1);
        mma_tf32(O[1][ntd], aP[1][0], aP[1][1], aP[1][2], aP[1][3], vb0, vb1);
      }
    }
  }

  #pragma unroll
  for (int s = 0; s < 4; ++s) {
    rsum[s] += __shfl_xor_sync(0xffffffffu, rsum[s], 1);
    rsum[s] += __shfl_xor_sync(0xffffffffu, rsum[s], 2);
  }
  if (qk == 0) {
    #pragma unroll
    for (int s = 0; s < 4; ++s) {
      int r = wm * 32 + (s >> 1) * 16 + (s & 1) * 8 + qrow;
      rowLp[wn * BM + r] = rsum[s];
    }
  }

  if (wn == 1) {
    #pragma unroll
    for (int mt = 0; mt < 2; ++mt) {
      const int r = wm * 32 + mt * 16 + qrow;
      #pragma unroll
      for (int ntd = 0; ntd < 4; ++ntd) {
        const int cb = ntd * 8 + 2 * qk;
        *reinterpret_cast<float2*>(&Obuf[r * OPITCH + cb]) =
            make_float2(O[mt][ntd][0], O[mt][ntd][1]);
        *reinterpret_cast<float2*>(&Obuf[(r + 8) * OPITCH + cb]) =
            make_float2(O[mt][ntd][2], O[mt][ntd][3]);
      }
    }
  }
  __syncthreads();

  if (tid < BM) {
    const int row = tid;
    const int t = t0 + row;
    const float* qt = base + (size_t)t * DH;
    float d0 = 0.f, d1 = 0.f, d2 = 0.f;
    #pragma unroll
    for (int kk = 0; kk < DH; ++kk) { float q = qt[kk]; d1 = fmaf(q, q, d1); }
    if (t > 0) {
      const float* km = base + (size_t)(t - 1) * DH;
      #pragma unroll
      for (int kk = 0; kk < DH; ++kk) d0 = fmaf(qt[kk], km[kk], d0);
    }
    if (t < MLEN - 1) {
      const float* kp = base + (size_t)(t + 1) * DH;
      #pragma unroll
      for (int kk = 0; kk < DH; ++kk) d2 = fmaf(qt[kk], kp[kk], d2);
    }
    float e0 = (t > 0)        ? d0 * scale2 : 0.0f;
    float e1 = d1 * scale2;
    float e2 = (t < MLEN - 1) ? d2 * scale2 : 0.0f;
    float p0 = ex2(e0), p1 = ex2(e1), p2 = ex2(e2);
    float L = rowLp[row] + rowLp[BM + row] + p0 + p1 + p2;
    pe0[row] = (t > 0)        ? p0 : 0.0f;
    pe1[row] = p1;
    pe2[row] = (t < MLEN - 1) ? p2 : 0.0f;
    linv[row] = 1.0f / L;
  }
  __syncthreads();

  if (wn == 0) {
    #pragma unroll
    for (int mt = 0; mt < 2; ++mt) {
      #pragma unroll
      for (int half = 0; half < 2; ++half) {
        const int r = wm * 32 + mt * 16 + half * 8 + qrow;
        const int t = t0 + r;
        const int n = 2 * t + rbit;
        if (n >= SEQ) continue;
        const float inv = linv[r];
        const float w0 = pe0[r], w1 = pe1[r], w2 = pe2[r];
        #pragma unroll
        for (int ntd = 0; ntd < 4; ++ntd) {
          const int cb = ntd * 8 + 2 * qk;
          float2 oo = *reinterpret_cast<const float2*>(&Obuf[r * OPITCH + cb]);
          float ax = O[mt][ntd][half * 2 + 0] + oo.x;
          float ay = O[mt][ntd][half * 2 + 1] + oo.y;
          float2 vc = *reinterpret_cast<const float2*>(&base[(size_t)t * DH + cb]);
          ax = fmaf(w1, vc.x, ax);
          ay = fmaf(w1, vc.y, ay);
          if (t > 0) {
            float2 vm = *reinterpret_cast<const float2*>(&base[(size_t)(t - 1) * DH + cb]);
            ax = fmaf(w0, vm.x, ax);
            ay = fmaf(w0, vm.y, ay);
          }
          if (t < MLEN - 1) {
            float2 vp = *reinterpret_cast<const float2*>(&base[(size_t)(t + 1) * DH + cb]);
            ax = fmaf(w2, vp.x, ax);
            ay = fmaf(w2, vp.y, ay);
          }
          *reinterpret_cast<float2*>(
              &out[((size_t)b * SEQ + n) * DMODEL + h * DH + cb]) =
              make_float2(ax * inv, ay * inv);
        }
      }
    }
  }
}

// ---------------------------------------------------------------------------
extern "C" void kernel_launch(void* const* d_in, const int* in_sizes, int n_in,
                              void* d_out, int out_size) {
  const float* x    = (const float*)d_in[0];
  const float* W    = (const float*)d_in[1];
  const float* bias = (const float*)d_in[2];
  float* out = (float*)d_out;

  qkv_gemm<<<dim3(BATCH * NPAD / 128, DMODEL / 64), 256>>>(x, W, bias);
  attn<<<NPROB * (MLEN / BM), 128>>>(out);
}

// round 17
// speedup vs baseline: 1.0325x; 1.0249x over previous
#include <cuda_runtime.h>
#include <cstdint>

#define HEADS   8
#define DH      32
#define MLEN    1024
#define NPROB   64          // B * HEADS * RATE
#define BATCH   4
#define SEQ     2046
#define NPAD    2048
#define DMODEL  256

#define BM      64
#define BN      64
#define OPITCH  34          // Obuf pitch

__device__ float g_qkv[NPROB * MLEN * DH];
__device__ uint32_t g_xt32[BATCH * NPAD * DMODEL];  // padded X in tf32 (rna)
__device__ uint32_t g_wt[DMODEL * DMODEL];          // W^T in tf32 (rna), [n][d]

// ---------------------------------------------------------------------------
// helpers
// ---------------------------------------------------------------------------
__device__ __forceinline__ uint32_t f2tf32(float f) {
  uint32_t u;
  asm("cvt.rna.tf32.f32 %0, %1;" : "=r"(u) : "f"(f));
  return u;
}

__device__ __forceinline__ float ex2(float x) {
  float r;
  asm("ex2.approx.f32 %0, %1;" : "=f"(r) : "f"(x));
  return r;
}

__device__ __forceinline__ void mma_tf32(float c[4],
    uint32_t a0, uint32_t a1, uint32_t a2, uint32_t a3,
    uint32_t b0, uint32_t b1) {
  asm volatile(
    "mma.sync.aligned.m16n8k8.row.col.f32.tf32.tf32.f32 "
    "{%0,%1,%2,%3},{%4,%5,%6,%7},{%8,%9},{%0,%1,%2,%3};"
    : "+f"(c[0]), "+f"(c[1]), "+f"(c[2]), "+f"(c[3])
    : "r"(a0), "r"(a1), "r"(a2), "r"(a3), "r"(b0), "r"(b1));
}

__device__ __forceinline__ void cp16(uint32_t dst_smem, const void* src) {
  asm volatile("cp.async.cg.shared.global [%0], [%1], 16;"
               :: "r"(dst_smem), "l"(src));
}
__device__ __forceinline__ void cp_commit() {
  asm volatile("cp.async.commit_group;");
}
__device__ __forceinline__ void cp_wait1() {
  asm volatile("cp.async.wait_group 1;");
}

// ---------------------------------------------------------------------------
// Kernel 0: prep — convert padded X -> tf32 (g_xt32) and W -> W^T tf32
// (g_wt) in one massively parallel launch. rna conversions identical to the
// ones previously done inside qkv_gemm -> bit-identical GEMM results.
// Grid: 2048 blocks for X (8192 rows x 64 float4) + 64 blocks for W.
// ---------------------------------------------------------------------------
__global__ __launch_bounds__(256) void prep(
    const float* __restrict__ x, const float* __restrict__ W) {
  const int blk = blockIdx.x;
  if (blk < 2048) {
    int idx = blk * 256 + threadIdx.x;       // float4 index, 524288 total
    int row = idx >> 6, c4 = (idx & 63) << 2;
    int b = row >> 11, n = row & 2047;
    uint4 u = make_uint4(0u, 0u, 0u, 0u);
    if (n < SEQ) {
      float4 v = *reinterpret_cast<const float4*>(
          x + ((size_t)b * SEQ + n) * DMODEL + c4);
      u.x = f2tf32(v.x); u.y = f2tf32(v.y);
      u.z = f2tf32(v.z); u.w = f2tf32(v.w);
    }
    *reinterpret_cast<uint4*>(&g_xt32[(size_t)row * DMODEL + c4]) = u;
  } else {
    int idx = (blk - 2048) * 256 + threadIdx.x;  // float4 index, 16384 total
    int d = idx >> 6, n4 = (idx & 63) << 2;
    float4 v = *reinterpret_cast<const float4*>(W + (size_t)d * DMODEL + n4);
    g_wt[(size_t)(n4 + 0) * DMODEL + d] = f2tf32(v.x);
    g_wt[(size_t)(n4 + 1) * DMODEL + d] = f2tf32(v.y);
    g_wt[(size_t)(n4 + 2) * DMODEL + d] = f2tf32(v.z);
    g_wt[(size_t)(n4 + 3) * DMODEL + d] = f2tf32(v.w);
  }
}

// ---------------------------------------------------------------------------
// Kernel 1: qkv = Xtf32 @ Wtf32^T + b — pure cp.async double-buffered
// pipeline (no register staging, no conversions). Prologue issues chunks
// 0,1; per chunk wait_group 1 gives a full chunk of latency slack.
// ---------------------------------------------------------------------------
__global__ __launch_bounds__(256) void qkv_gemm(const float* __restrict__ bias) {
  __shared__ __align__(16) uint32_t Xs[2][128 * 32];  // 32 KB
  __shared__ __align__(16) uint32_t Ws[2][64 * 32];   // 16 KB
  const int m0 = blockIdx.x * 128;
  const int n0 = blockIdx.y * 64;
  const int tid = threadIdx.x;
  const int warp = tid >> 5, lane = tid & 31;
  const int wm = warp >> 1, wn = warp & 1;
  const int qrow = lane >> 2, qk = lane & 3;
  const uint32_t swzA = (uint32_t)(qrow << 2);

  const uint32_t xsBase = (uint32_t)__cvta_generic_to_shared(&Xs[0][0]);
  const uint32_t wsBase = (uint32_t)__cvta_generic_to_shared(&Ws[0][0]);

  auto issueChunk = [&](int kc, int buf) {
    const int kc0 = kc * 32;
    const uint32_t xd = xsBase + (uint32_t)(buf * 128 * 32) * 4;
    const uint32_t wd = wsBase + (uint32_t)(buf * 64 * 32) * 4;
    #pragma unroll
    for (int e = 0; e < 4; ++e) {
      int f = tid + 256 * e;            // 1024 float4 groups
      int r = f >> 3, c4 = (f & 7) << 2;
      cp16(xd + (uint32_t)(r * 32 + (c4 ^ ((r & 7) << 2))) * 4,
           g_xt32 + (size_t)(m0 + r) * DMODEL + kc0 + c4);
    }
    #pragma unroll
    for (int e = 0; e < 2; ++e) {
      int f = tid + 256 * e;            // 512 float4 groups
      int r = f >> 3, c4 = (f & 7) << 2;
      cp16(wd + (uint32_t)(r * 32 + (c4 ^ ((r & 7) << 2))) * 4,
           g_wt + (size_t)(n0 + r) * DMODEL + kc0 + c4);
    }
  };

  issueChunk(0, 0); cp_commit();
  issueChunk(1, 1); cp_commit();

  float C[2][4][4];
  #pragma unroll
  for (int i = 0; i < 2; ++i)
    #pragma unroll
    for (int j = 0; j < 4; ++j)
      #pragma unroll
      for (int k = 0; k < 4; ++k) C[i][j][k] = 0.0f;

  for (int kc = 0; kc < 8; ++kc) {
    cp_wait1();        // chunk kc complete; kc+1 may still be in flight
    __syncthreads();   // publish chunk kc; also: prior readers of buf done

    const uint32_t* Xc = Xs[kc & 1];
    const uint32_t* Wc = Ws[kc & 1];
    #pragma unroll
    for (int ks = 0; ks < 4; ++ks) {
      const int k0 = ks * 8 + qk;
      uint32_t a[2][4];
      #pragma unroll
      for (int mt = 0; mt < 2; ++mt) {
        const int rb = wm * 32 + mt * 16 + qrow;
        a[mt][0] = Xc[rb * 32 + (k0 ^ swzA)];
        a[mt][1] = Xc[(rb + 8) * 32 + (k0 ^ swzA)];
        a[mt][2] = Xc[rb * 32 + ((k0 + 4) ^ swzA)];
        a[mt][3] = Xc[(rb + 8) * 32 + ((k0 + 4) ^ swzA)];
      }
      uint32_t bf[4][2];
      #pragma unroll
      for (int nt = 0; nt < 4; ++nt) {
        const int nc = wn * 32 + nt * 8 + qrow;
        bf[nt][0] = Wc[nc * 32 + (k0 ^ swzA)];
        bf[nt][1] = Wc[nc * 32 + ((k0 + 4) ^ swzA)];
      }
      #pragma unroll
      for (int mt = 0; mt < 2; ++mt)
        #pragma unroll
        for (int nt = 0; nt < 4; ++nt)
          mma_tf32(C[mt][nt], a[mt][0], a[mt][1], a[mt][2], a[mt][3],
                   bf[nt][0], bf[nt][1]);
    }

    __syncthreads();   // all warps done reading buf kc&1 before refilling it
    if (kc + 2 < 8) issueChunk(kc + 2, kc & 1);
    cp_commit();       // one group per iteration (may be empty near the end)
  }

  #pragma unroll
  for (int nt = 0; nt < 4; ++nt) {
    const int col = n0 + wn * 32 + nt * 8 + 2 * qk;
    const float bx = bias[col], by = bias[col + 1];
    const int h = col >> 5, dd = col & 31;
    #pragma unroll
    for (int mt = 0; mt < 2; ++mt) {
      #pragma unroll
      for (int half = 0; half < 2; ++half) {
        const int r = wm * 32 + mt * 16 + half * 8 + qrow;
        const int m = m0 + r;
        const int b = m >> 11, n = m & 2047;
        const int i = n >> 1, rbit = n & 1;
        float2 val = make_float2(C[mt][nt][half * 2 + 0] + bx,
                                 C[mt][nt][half * 2 + 1] + by);
        *reinterpret_cast<float2*>(
            &g_qkv[((((size_t)b * HEADS + h) * 2 + rbit) * MLEN + i) * DH + dd]) =
            val;
      }
    }
  }
}

// ---------------------------------------------------------------------------
// Kernel 2: flash attention — byte-identical to R16 (triple-buffered tiles,
// wait_group 1 at loop top, one barrier per tile; raw-bit P, ex2.approx).
// ---------------------------------------------------------------------------
__global__ __launch_bounds__(128, 4) void attn(float* __restrict__ out) {
  const int blk  = blockIdx.x;
  const int prob = blk >> 4;
  const int tile = blk & 15;
  const int t0   = tile * BM;
  const int rbit = prob & 1;
  const int h    = (prob >> 1) & 7;
  const int b    = prob >> 4;
  const float* __restrict__ base = g_qkv + (size_t)prob * (MLEN * DH);
  const int tid  = threadIdx.x;
  const int warp = tid >> 5, lane = tid & 31;
  const int wm = warp >> 1, wn = warp & 1;
  const int qrow = lane >> 2, qk = lane & 3;
  const uint32_t swzA = (uint32_t)(qrow << 2);
  const float scale2 = 0.17677669529663687f * 1.4426950408889634f;

  __shared__ __align__(16) char KsObuf[BM * OPITCH * 4];   // Ks then Obuf
  __shared__ __align__(16) uint32_t Qs[3][BN * 32];        // triple buffer
  __shared__ float rowLp[2 * BM];
  __shared__ float pe0[BM], pe1[BM], pe2[BM], linv[BM];
  uint32_t* Ks  = reinterpret_cast<uint32_t*>(KsObuf);
  float*   Obuf = reinterpret_cast<float*>(KsObuf);

  const uint32_t qsBase = (uint32_t)__cvta_generic_to_shared(&Qs[0][0]);

  auto issueTile = [&](int it, int buf) {
    const float* src = base + (size_t)it * BN * DH;
    const uint32_t dst = qsBase + (uint32_t)(buf * BN * 32) * 4;
    #pragma unroll
    for (int e = 0; e < 4; ++e) {
      int f = tid + 128 * e;
      int r = f >> 3, c = (f & 7) << 2;
      cp16(dst + (uint32_t)(r * 32 + (c ^ ((r & 7) << 2))) * 4,
           src + r * 32 + c);
    }
  };

  issueTile(0, 0); cp_commit();
  issueTile(1, 1); cp_commit();

  #pragma unroll
  for (int e = 0; e < 4; ++e) {
    int f = tid + 128 * e;
    int r = f >> 3, c = (f & 7) << 2;
    float4 v = *reinterpret_cast<const float4*>(base + (size_t)(t0 + r) * DH + c);
    uint4 u;
    u.x = f2tf32(v.x * scale2); u.y = f2tf32(v.y * scale2);
    u.z = f2tf32(v.z * scale2); u.w = f2tf32(v.w * scale2);
    *reinterpret_cast<uint4*>(&Ks[r * 32 + (c ^ ((r & 7) << 2))]) = u;
  }
  __syncthreads();

  uint32_t A[2][4][4];
  #pragma unroll
  for (int mt = 0; mt < 2; ++mt) {
    const int rb = wm * 32 + mt * 16 + qrow;
    #pragma unroll
    for (int kc = 0; kc < 4; ++kc) {
      const int k0 = kc * 8 + qk;
      A[mt][kc][0] = Ks[rb * 32 + (k0 ^ swzA)];
      A[mt][kc][1] = Ks[(rb + 8) * 32 + (k0 ^ swzA)];
      A[mt][kc][2] = Ks[rb * 32 + ((k0 + 4) ^ swzA)];
      A[mt][kc][3] = Ks[(rb + 8) * 32 + ((k0 + 4) ^ swzA)];
    }
  }
  __syncthreads();   // all warps done reading Ks before Obuf writes

  float O[2][4][4];
  #pragma unroll
  for (int i = 0; i < 2; ++i)
    #pragma unroll
    for (int j = 0; j < 4; ++j)
      #pragma unroll
      for (int k = 0; k < 4; ++k) O[i][j][k] = 0.0f;
  float rsum[4] = {0.f, 0.f, 0.f, 0.f};

  for (int it = 0; it < MLEN / BN; ++it) {
    cp_wait1();
    __syncthreads();

    if (it + 2 < MLEN / BN) issueTile(it + 2, (it + 2) % 3);
    cp_commit();

    const uint32_t* __restrict__ Qc = &Qs[it % 3][0];

    #pragma unroll
    for (int g = 0; g < 4; ++g) {
      float acc[2][4] = {{0.f,0.f,0.f,0.f},{0.f,0.f,0.f,0.f}};
      const int nc = wn * 32 + g * 8 + qrow;
      #pragma unroll
      for (int kc = 0; kc < 4; ++kc) {
        const int k0 = kc * 8 + qk;
        uint32_t b0 = Qc[nc * 32 + (k0 ^ swzA)];
        uint32_t b1 = Qc[nc * 32 + ((k0 + 4) ^ swzA)];
        mma_tf32(acc[0], A[0][kc][0], A[0][kc][1], A[0][kc][2], A[0][kc][3], b0, b1);
        mma_tf32(acc[1], A[1][kc][0], A[1][kc][1], A[1][kc][2], A[1][kc][3], b0, b1);
      }

      uint32_t aP[2][4];
      #pragma unroll
      for (int mt = 0; mt < 2; ++mt) {
        float p0 = ex2(acc[mt][0]);
        float p1 = ex2(acc[mt][1]);
        float p2 = ex2(acc[mt][2]);
        float p3 = ex2(acc[mt][3]);
        rsum[mt * 2 + 0] += p0 + p1;
        rsum[mt * 2 + 1] += p2 + p3;
        aP[mt][0] = __float_as_uint(p0);
        aP[mt][1] = __float_as_uint(p2);
        aP[mt][2] = __float_as_uint(p1);
        aP[mt][3] = __float_as_uint(p3);
      }

      const int jr0 = wn * 32 + g * 8 + 2 * qk;
      const int jr1 = jr0 + 1;
      const uint32_t swz0 = (uint32_t)((jr0 & 7) << 2);
      const uint32_t swz1 = (uint32_t)((jr1 & 7) << 2);
      #pragma unroll
      for (int ntd = 0; ntd < 4; ++ntd) {
        const int d = ntd * 8 + qrow;
        uint32_t vb0 = Qc[jr0 * 32 + (d ^ swz0)];
        uint32_t vb1 = Qc[jr1 * 32 + (d ^ swz1)];
        mma_tf32(O[0][ntd], aP[0][0], aP[0][1], aP[0][2], aP[0][3], vb0, vb1);
        mma_tf32(O[1][ntd], aP[1][0], aP[1][1], aP[1][2], aP[1][3], vb0, vb1);
      }
    }
  }

  #pragma unroll
  for (int s = 0; s < 4; ++s) {
    rsum[s] += __shfl_xor_sync(0xffffffffu, rsum[s], 1);
    rsum[s] += __shfl_xor_sync(0xffffffffu, rsum[s], 2);
  }
  if (qk == 0) {
    #pragma unroll
    for (int s = 0; s < 4; ++s) {
      int r = wm * 32 + (s >> 1) * 16 + (s & 1) * 8 + qrow;
      rowLp[wn * BM + r] = rsum[s];
    }
  }

  if (wn == 1) {
    #pragma unroll
    for (int mt = 0; mt < 2; ++mt) {
      const int r = wm * 32 + mt * 16 + qrow;
      #pragma unroll
      for (int ntd = 0; ntd < 4; ++ntd) {
        const int cb = ntd * 8 + 2 * qk;
        *reinterpret_cast<float2*>(&Obuf[r * OPITCH + cb]) =
            make_float2(O[mt][ntd][0], O[mt][ntd][1]);
        *reinterpret_cast<float2*>(&Obuf[(r + 8) * OPITCH + cb]) =
            make_float2(O[mt][ntd][2], O[mt][ntd][3]);
      }
    }
  }
  __syncthreads();

  if (tid < BM) {
    const int row = tid;
    const int t = t0 + row;
    const float* qt = base + (size_t)t * DH;
    float d0 = 0.f, d1 = 0.f, d2 = 0.f;
    #pragma unroll
    for (int kk = 0; kk < DH; ++kk) { float q = qt[kk]; d1 = fmaf(q, q, d1); }
    if (t > 0) {
      const float* km = base + (size_t)(t - 1) * DH;
      #pragma unroll
      for (int kk = 0; kk < DH; ++kk) d0 = fmaf(qt[kk], km[kk], d0);
    }
    if (t < MLEN - 1) {
      const float* kp = base + (size_t)(t + 1) * DH;
      #pragma unroll
      for (int kk = 0; kk < DH; ++kk) d2 = fmaf(qt[kk], kp[kk], d2);
    }
    float e0 = (t > 0)        ? d0 * scale2 : 0.0f;
    float e1 = d1 * scale2;
    float e2 = (t < MLEN - 1) ? d2 * scale2 : 0.0f;
    float p0 = ex2(e0), p1 = ex2(e1), p2 = ex2(e2);
    float L = rowLp[row] + rowLp[BM + row] + p0 + p1 + p2;
    pe0[row] = (t > 0)        ? p0 : 0.0f;
    pe1[row] = p1;
    pe2[row] = (t < MLEN - 1) ? p2 : 0.0f;
    linv[row] = 1.0f / L;
  }
  __syncthreads();

  if (wn == 0) {
    #pragma unroll
    for (int mt = 0; mt < 2; ++mt) {
      #pragma unroll
      for (int half = 0; half < 2; ++half) {
        const int r = wm * 32 + mt * 16 + half * 8 + qrow;
        const int t = t0 + r;
        const int n = 2 * t + rbit;
        if (n >= SEQ) continue;
        const float inv = linv[r];
        const float w0 = pe0[r], w1 = pe1[r], w2 = pe2[r];
        #pragma unroll
        for (int ntd = 0; ntd < 4; ++ntd) {
          const int cb = ntd * 8 + 2 * qk;
          float2 oo = *reinterpret_cast<const float2*>(&Obuf[r * OPITCH + cb]);
          float ax = O[mt][ntd][half * 2 + 0] + oo.x;
          float ay = O[mt][ntd][half * 2 + 1] + oo.y;
          float2 vc = *reinterpret_cast<const float2*>(&base[(size_t)t * DH + cb]);
          ax = fmaf(w1, vc.x, ax);
          ay = fmaf(w1, vc.y, ay);
          if (t > 0) {
            float2 vm = *reinterpret_cast<const float2*>(&base[(size_t)(t - 1) * DH + cb]);
            ax = fmaf(w0, vm.x, ax);
            ay = fmaf(w0, vm.y, ay);
          }
          if (t < MLEN - 1) {
            float2 vp = *reinterpret_cast<const float2*>(&base[(size_t)(t + 1) * DH + cb]);
            ax = fmaf(w2, vp.x, ax);
            ay = fmaf(w2, vp.y, ay);
          }
          *reinterpret_cast<float2*>(
              &out[((size_t)b * SEQ + n) * DMODEL + h * DH + cb]) =
              make_float2(ax * inv, ay * inv);
        }
      }
    }
  }
}

// ---------------------------------------------------------------------------
extern "C" void kernel_launch(void* const* d_in, const int* in_sizes, int n_in,
                              void* d_out, int out_size) {
  const float* x    = (const float*)d_in[0];
  const float* W    = (const float*)d_in[1];
  const float* bias = (const float*)d_in[2];
  float* out = (float*)d_out;

  prep<<<2048 + 64, 256>>>(x, W);
  qkv_gemm<<<dim3(BATCH * NPAD / 128, DMODEL / 64), 256>>>(bias);
  attn<<<NPROB * (MLEN / BM), 128>>>(out);
}